// round 11
// baseline (speedup 1.0000x reference)
#include <cuda_runtime.h>
#include <cuda_bf16.h>
#include <math.h>

#define Hh 64
#define Ff 10
#define Tt 60
#define Dd 6
#define Bb 2048

typedef unsigned long long ull;

// bf16 recurrent weights as natural (gate0,gate1) pairs, per gate-role g:
//   g=0: (G0,G1) = (U_i,U_ste);  g=1: (U_c,U_o)
// g_Ub2[g][j*32+lane] = { bf16x2(G0,G1)@h=lane , bf16x2(G0,G1)@h=lane+32 }
__device__ ull g_Ub2[2][Hh * 32];

__device__ __forceinline__ unsigned int bpack(float a, float b) {
    __nv_bfloat162 p = __floats2bfloat162_rn(a, b);
    return *reinterpret_cast<unsigned int*>(&p);
}

__global__ void prep_kernel(const float* __restrict__ Ui, const float* __restrict__ Us,
                            const float* __restrict__ Uc, const float* __restrict__ Uo) {
    int idx = blockIdx.x * blockDim.x + threadIdx.x;   // [0, 2*64*32)
    if (idx < 2 * Hh * 32) {
        int g = idx >> 11, r = idx & 2047;
        int j = r >> 5, lane = r & 31;
        const float* G0 = g ? Uc : Ui;
        const float* G1 = g ? Uo : Us;
        unsigned int lo = bpack(G0[j * Hh + lane],      G1[j * Hh + lane]);
        unsigned int hi = bpack(G0[j * Hh + lane + 32], G1[j * Hh + lane + 32]);
        g_Ub2[g][r] = ((ull)hi << 32) | (ull)lo;
    }
}

__device__ __forceinline__ float hsig(float v) {
    return __saturatef(fmaf(v, 0.16666667f, 0.5f));
}
__device__ __forceinline__ ull pack2(float lo, float hi) {
    ull r; asm("mov.b64 %0, {%1, %2};" : "=l"(r) : "f"(lo), "f"(hi)); return r;
}
__device__ __forceinline__ ull fma2(ull a, ull b, ull c) {
    ull d; asm("fma.rn.f32x2 %0, %1, %2, %3;" : "=l"(d) : "l"(a), "l"(b), "l"(c)); return d;
}
__device__ __forceinline__ ull add2(ull a, ull b) {
    ull d; asm("add.rn.f32x2 %0, %1, %2;" : "=l"(d) : "l"(a), "l"(b)); return d;
}
__device__ __forceinline__ float2 unpack2(ull v) {
    float lo, hi; asm("mov.b64 {%0, %1}, %2;" : "=f"(lo), "=f"(hi) : "l"(v));
    return make_float2(lo, hi);
}
// bf16x2(G0,G1) -> f32x2 (G0,G1): 2 ALU ops (latency filler between LDS and FFMA2).
__device__ __forceinline__ ull bf2f2(unsigned int u) {
    float lo = __uint_as_float(u << 16);
    float hi = __uint_as_float(u & 0xFFFF0000u);
    return pack2(lo, hi);
}
// tanh(x) = 1 - 2/(exp(2x)+1): MUFU.EX2 + MUFU.RCP, abs err ~1e-6
__device__ __forceinline__ float ftanh(float x) {
    float e = __expf(2.0f * x);
    float r;
    asm("rcp.approx.f32 %0, %1;" : "=f"(r) : "f"(e + 1.0f));
    return fmaf(-2.0f, r, 1.0f);
}

// Block = 128 threads = 4 warps over (gate-pair g = w&1, batch-pair bp = w>>1),
// 4 batches per block. Warp w computes its gate pair for its 2 batches,
// owns batch w for the elementwise tail + fre. Lane owns columns {lane, lane+32}.
// U (bf16) staged once into shared, serves all 4 warps.
__global__ __launch_bounds__(128) void sfm_kernel(
    const float* __restrict__ x,
    const float* __restrict__ W_i,   const float* __restrict__ b_i,
    const float* __restrict__ W_ste, const float* __restrict__ b_ste,
    const float* __restrict__ W_fre, const float* __restrict__ U_fre, const float* __restrict__ b_fre,
    const float* __restrict__ W_c,   const float* __restrict__ b_c,
    const float* __restrict__ W_o,   const float* __restrict__ b_o,
    const float* __restrict__ U_a,   const float* __restrict__ b_a,
    const float* __restrict__ W_p,   const float* __restrict__ b_p,
    float* __restrict__ out)
{
    __shared__ __align__(16) uint2  sh_Ub[2][Hh][32];  // bf16 U, 32 KB (per gate-pair)
    __shared__ __align__(16) float4 sh_x4[Tt][Dd];     // (b0,b1,b2,b3)
    __shared__ __align__(16) ull    sh_hd[Hh][4];      // dup (h,h) pairs [col][b]
    __shared__ __align__(16) ull    sh_ex[4][32][2];   // exchange [writer w][lane][hs]
    __shared__ float                sh_UfT[Ff * 65];   // [f][j], padded rows
    __shared__ ull                  sh_mpk[Tt];        // packed nibble idx m(t,f)
    __shared__ __align__(8) float2  sh_tbl[16];        // 10 distinct (cos,sin)

    const int tid  = threadIdx.x;
    const int lane = tid & 31;
    const int w    = tid >> 5;
    const int g    = w & 1;              // gate pair: 0 = (i,ste), 1 = (c,o)
    const int bp   = w >> 1;             // batch pair: 0 = (b0,b1), 1 = (b2,b3)
    const int bbase = blockIdx.x * 4;

    // ---- one-time staging ----
    {   // U: 2048 uint4 = 32 KB
        const uint4* gsrc = reinterpret_cast<const uint4*>(&g_Ub2[0][0]);
        uint4* sdst = reinterpret_cast<uint4*>(&sh_Ub[0][0][0]);
        for (int i = tid; i < 2 * Hh * 32 / 2; i += 128) sdst[i] = gsrc[i];
    }
    const float* xg = x + (size_t)bbase * (Tt * Dd);
    for (int i = tid; i < Tt * Dd; i += 128) {
        sh_x4[i / Dd][i % Dd] = make_float4(xg[0 * Tt * Dd + i], xg[1 * Tt * Dd + i],
                                            xg[2 * Tt * Dd + i], xg[3 * Tt * Dd + i]);
    }
    for (int i = tid; i < Ff * Hh; i += 128) {
        int f = i >> 6, j = i & 63;
        sh_UfT[f * 65 + j] = U_fre[j * Ff + f];
    }
    for (int i = tid; i < Tt; i += 128) {
        ull v = 0;
#pragma unroll
        for (int f = 1; f < Ff; f++)
            v |= (ull)(((i + 1) * f) % Ff) << (4 * f);
        sh_mpk[i] = v;
    }
    if (tid < Ff) {
        float s, c;
        sincosf((float)tid * 0.62831853071795864769f, &s, &c);   // 2*pi/10
        sh_tbl[tid] = make_float2(c, s);
    }
    if (tid < Hh) {
#pragma unroll
        for (int b = 0; b < 4; b++) sh_hd[tid][b] = 0ull;
    }

    // ---- per-lane constants ----
    const int h0 = lane, h1 = lane + 32;
    const float* Wg0 = g ? W_c : W_i;
    const float* Wg1 = g ? W_o : W_ste;
    const float* bg0 = g ? b_c : b_i;
    const float* bg1 = g ? b_o : b_ste;
    ull Wp_[2][Dd];   // W as natural (g0,g1) pairs: [hslot][d]
#pragma unroll
    for (int d = 0; d < Dd; d++) {
        Wp_[0][d] = pack2(Wg0[d * Hh + h0], Wg1[d * Hh + h0]);
        Wp_[1][d] = pack2(Wg0[d * Hh + h1], Wg1[d * Hh + h1]);
    }
    const ull bp_[2] = { pack2(bg0[h0], bg1[h0]), pack2(bg0[h1], bg1[h1]) };
    const float ba_[2] = { b_a[h0], b_a[h1] };
    float ua[Ff];
#pragma unroll
    for (int f = 0; f < Ff; f++) ua[f] = U_a[f];

    // fre duty: lanes 0..9 of each warp; f = lane, batch = w.
    const bool duty = (lane < Ff);
    float wfre[Dd];
#pragma unroll
    for (int d = 0; d < Dd; d++) wfre[d] = W_fre[d * Ff + lane % Ff];
    const float bfre = b_fre[lane % Ff];

    // Oscillator state for my 1 tail batch (w): [hslot][f]
    float sre[2][Ff], sim[2][Ff];
#pragma unroll
    for (int hs = 0; hs < 2; hs++)
#pragma unroll
        for (int f = 0; f < Ff; f++) { sre[hs][f] = 0.0f; sim[hs][f] = 0.0f; }

    float hlast[2];   // [hslot], my batch's h (epilogue + publish)

    __syncthreads();

    for (int t = 0; t < Tt; t++) {
        // ---- seeds: acc[hs][bl] = (g0,g1) bias + x_t @ (Wg0,Wg1), my 2 batches ----
        ull acc[2][2];
        acc[0][0] = bp_[0]; acc[0][1] = bp_[0];
        acc[1][0] = bp_[1]; acc[1][1] = bp_[1];
        float af = bfre;
#pragma unroll
        for (int d = 0; d < Dd; d++) {
            float4 xv = sh_x4[t][d];             // LDS.128 broadcast
            float xe = bp ? xv.z : xv.x;         // my even batch
            float xo = bp ? xv.w : xv.y;         // my odd batch
            ull xd0 = pack2(xe, xe);
            ull xd1 = pack2(xo, xo);
            acc[0][0] = fma2(xd0, Wp_[0][d], acc[0][0]);
            acc[1][0] = fma2(xd0, Wp_[1][d], acc[1][0]);
            acc[0][1] = fma2(xd1, Wp_[0][d], acc[0][1]);
            acc[1][1] = fma2(xd1, Wp_[1][d], acc[1][1]);
            af = fmaf(g ? xo : xe, wfre[d], af);  // my tail batch = pair-slot g
        }

        // ---- recurrent matmul: bf16 U (LDS.64) x my batch-pair's dup-h (LDS.128) ----
#pragma unroll 8
        for (int j = 0; j < Hh; j++) {
            uint2 uu = sh_Ub[g][j][lane];                            // LDS.64, conflict-free
            ulonglong2 hA = *(const ulonglong2*)&sh_hd[j][2 * bp];   // my pair's (ee, oo)
            ull u0 = bf2f2(uu.x);                                    // (g0,g1) @ h0
            ull u1 = bf2f2(uu.y);                                    // (g0,g1) @ h1
            acc[0][0] = fma2(hA.x, u0, acc[0][0]);
            acc[1][0] = fma2(hA.x, u1, acc[1][0]);
            acc[0][1] = fma2(hA.y, u0, acc[0][1]);
            acc[1][1] = fma2(hA.y, u1, acc[1][1]);
            if (duty) {
                ull hown = g ? hA.y : hA.x;      // my tail batch's dup pair
                af = fmaf(unpack2(hown).x, sh_UfT[lane * 65 + j], af);
            }
        }
        const float frev = hsig(af);   // fre[w][lane] on duty lanes

        // ---- exchange: publish my gate pair for the batch I do NOT own (pair-slot 1-g) ----
        {
            ulonglong2* dst = reinterpret_cast<ulonglong2*>(&sh_ex[w][lane][0]);
            *dst = make_ulonglong2(acc[0][1 - g], acc[1][1 - g]);
        }
        __syncthreads();   // exchange visible; sh_hd reads of this step done
        ull peer0, peer1;  // other gate pair for MY batch, per hslot
        {
            const ulonglong2* src = reinterpret_cast<const ulonglong2*>(&sh_ex[w ^ 1][lane][0]);
            ulonglong2 s = *src;
            peer0 = s.x; peer1 = s.y;
        }

        // ---- elementwise tail for my batch (w), 2 columns ----
        float cs[Ff], sn[Ff];
        {
            ull mp = sh_mpk[t];
#pragma unroll
            for (int f = 0; f < Ff; f++) {
                float2 cn = sh_tbl[(int)((mp >> (4 * f)) & 15)];
                cs[f] = cn.x; sn[f] = cn.y;
            }
        }
#pragma unroll
        for (int hs = 0; hs < 2; hs++) {
            float2 mine = unpack2(acc[hs][g]);            // my gates @ my batch
            float2 thrs = unpack2(hs ? peer1 : peer0);    // peer gates @ my batch
            float pi   = g ? thrs.x : mine.x;
            float pste = g ? thrs.y : mine.y;
            float pc   = g ? mine.x : thrs.x;
            float po   = g ? mine.y : thrs.y;
            float iv = hsig(pi);
            float sv = hsig(pste);
            float ov = hsig(po);
            float cv = iv * ftanh(pc);
            float acca = ba_[hs];
#pragma unroll
            for (int f = 0; f < Ff; f++) {
                float frf = __shfl_sync(0xffffffffu, frev, f);
                float fv = sv * frf;
                float r = fmaf(fv, sre[hs][f], cv * cs[f]);
                float m = fmaf(fv, sim[hs][f], cv * sn[f]);
                sre[hs][f] = r;
                sim[hs][f] = m;
                acca = fmaf(fmaf(r, r, m * m), ua[f], acca);
            }
            hlast[hs] = ov * ftanh(acca);
        }
        // Publish my batch's h as dup pairs at both columns.
        sh_hd[h0][w] = pack2(hlast[0], hlast[0]);
        sh_hd[h1][w] = pack2(hlast[1], hlast[1]);
        __syncthreads();   // new h visible for next step
    }

    // ---- projection: out[bbase+w] = h_w @ W_p + b_p (warp butterfly) ----
    {
        float p = fmaf(hlast[0], W_p[h0], hlast[1] * W_p[h1]);
#pragma unroll
        for (int off = 16; off >= 1; off >>= 1)
            p += __shfl_xor_sync(0xffffffffu, p, off);
        if (lane == 0) out[bbase + w] = p + b_p[0];
    }
}

extern "C" void kernel_launch(void* const* d_in, const int* in_sizes, int n_in,
                              void* d_out, int out_size) {
    const float* x     = (const float*)d_in[0];
    const float* W_i   = (const float*)d_in[1];
    const float* U_i   = (const float*)d_in[2];
    const float* b_i   = (const float*)d_in[3];
    const float* W_ste = (const float*)d_in[4];
    const float* U_ste = (const float*)d_in[5];
    const float* b_ste = (const float*)d_in[6];
    const float* W_fre = (const float*)d_in[7];
    const float* U_fre = (const float*)d_in[8];
    const float* b_fre = (const float*)d_in[9];
    const float* W_c   = (const float*)d_in[10];
    const float* U_c   = (const float*)d_in[11];
    const float* b_c   = (const float*)d_in[12];
    const float* W_o   = (const float*)d_in[13];
    const float* U_o   = (const float*)d_in[14];
    const float* b_o   = (const float*)d_in[15];
    const float* U_a   = (const float*)d_in[16];
    const float* b_a   = (const float*)d_in[17];
    const float* W_p   = (const float*)d_in[18];
    const float* b_p   = (const float*)d_in[19];

    (void)in_sizes; (void)n_in; (void)out_size;

    prep_kernel<<<(2 * Hh * 32 + 255) / 256, 256>>>(U_i, U_ste, U_c, U_o);
    sfm_kernel<<<Bb / 4, 128>>>(x, W_i, b_i, W_ste, b_ste, W_fre, U_fre, b_fre,
                                W_c, b_c, W_o, b_o, U_a, b_a, W_p, b_p,
                                (float*)d_out);
}

// round 12
// speedup vs baseline: 1.2742x; 1.2742x over previous
#include <cuda_runtime.h>
#include <cuda_bf16.h>
#include <math.h>

#define Hh 64
#define Ff 10
#define Tt 60
#define Dd 6
#define Bb 2048

typedef unsigned long long ull;

// bf16 recurrent weights, 2 j's per uint4, per gate-role g:
//   g=0: (G0,G1) = (U_i,U_ste);  g=1: (U_c,U_o)
// g_Ub4[g][jp*32+lane] = { bf16x2(G0,G1)@j0,h0 ; @j0,h1 ; @j1,h0 ; @j1,h1 }, j0=2jp, j1=2jp+1
__device__ uint4 g_Ub4[2][32 * 32];

__device__ __forceinline__ unsigned int bpack(float a, float b) {
    __nv_bfloat162 p = __floats2bfloat162_rn(a, b);
    return *reinterpret_cast<unsigned int*>(&p);
}

__global__ void prep_kernel(const float* __restrict__ Ui, const float* __restrict__ Us,
                            const float* __restrict__ Uc, const float* __restrict__ Uo) {
    int idx = blockIdx.x * blockDim.x + threadIdx.x;   // [0, 2*32*32)
    if (idx < 2 * 32 * 32) {
        int g = idx >> 10, r = idx & 1023;
        int jp = r >> 5, lane = r & 31;
        int j0 = 2 * jp, j1 = 2 * jp + 1;
        const float* G0 = g ? Uc : Ui;
        const float* G1 = g ? Uo : Us;
        uint4 v;
        v.x = bpack(G0[j0 * Hh + lane],      G1[j0 * Hh + lane]);
        v.y = bpack(G0[j0 * Hh + lane + 32], G1[j0 * Hh + lane + 32]);
        v.z = bpack(G0[j1 * Hh + lane],      G1[j1 * Hh + lane]);
        v.w = bpack(G0[j1 * Hh + lane + 32], G1[j1 * Hh + lane + 32]);
        g_Ub4[g][r] = v;
    }
}

__device__ __forceinline__ float hsig(float v) {
    return __saturatef(fmaf(v, 0.16666667f, 0.5f));
}
__device__ __forceinline__ ull pack2(float lo, float hi) {
    ull r; asm("mov.b64 %0, {%1, %2};" : "=l"(r) : "f"(lo), "f"(hi)); return r;
}
__device__ __forceinline__ ull fma2(ull a, ull b, ull c) {
    ull d; asm("fma.rn.f32x2 %0, %1, %2, %3;" : "=l"(d) : "l"(a), "l"(b), "l"(c)); return d;
}
__device__ __forceinline__ ull mul2(ull a, ull b) {
    ull d; asm("mul.rn.f32x2 %0, %1, %2;" : "=l"(d) : "l"(a), "l"(b)); return d;
}
__device__ __forceinline__ ull add2(ull a, ull b) {
    ull d; asm("add.rn.f32x2 %0, %1, %2;" : "=l"(d) : "l"(a), "l"(b)); return d;
}
__device__ __forceinline__ float2 unpack2(ull v) {
    float lo, hi; asm("mov.b64 {%0, %1}, %2;" : "=f"(lo), "=f"(hi) : "l"(v));
    return make_float2(lo, hi);
}
// bf16x2(G0,G1) -> f32x2 (G0,G1): 2 ALU ops (latency filler between LDS and FFMA2).
__device__ __forceinline__ ull bf2f2(unsigned int u) {
    float lo = __uint_as_float(u << 16);
    float hi = __uint_as_float(u & 0xFFFF0000u);
    return pack2(lo, hi);
}
// tanh(x) = 1 - 2/(exp(2x)+1): MUFU.EX2 + MUFU.RCP, abs err ~1e-6
__device__ __forceinline__ float ftanh(float x) {
    float e = __expf(2.0f * x);
    float r;
    asm("rcp.approx.f32 %0, %1;" : "=f"(r) : "f"(e + 1.0f));
    return fmaf(-2.0f, r, 1.0f);
}

// Block = 64 threads = 2 gate-split warps sharing 4 batches (R10 structure).
// Warp 0 computes gates (i,ste) for all 4 batches; warp 1 computes (c,o).
// Warp w runs the elementwise tail + fre for batches {2w, 2w+1}.
// Lane owns h-columns {lane, lane+32}. U (bf16) staged once into shared.
__global__ __launch_bounds__(64) void sfm_kernel(
    const float* __restrict__ x,
    const float* __restrict__ W_i,   const float* __restrict__ b_i,
    const float* __restrict__ W_ste, const float* __restrict__ b_ste,
    const float* __restrict__ W_fre, const float* __restrict__ U_fre, const float* __restrict__ b_fre,
    const float* __restrict__ W_c,   const float* __restrict__ b_c,
    const float* __restrict__ W_o,   const float* __restrict__ b_o,
    const float* __restrict__ U_a,   const float* __restrict__ b_a,
    const float* __restrict__ W_p,   const float* __restrict__ b_p,
    float* __restrict__ out)
{
    __shared__ __align__(16) uint4  sh_Ub[2][32][32];  // bf16 U, 2 j's per uint4, 32 KB
    __shared__ __align__(16) float4 sh_x4[Tt][Dd];     // (b0,b1,b2,b3)
    __shared__ __align__(16) ull    sh_hd[Hh][4];      // dup (h,h) pairs [col][b]
    __shared__ __align__(16) ull    sh_ex[2][32][4];   // gate exchange [writer][lane][hs*2+bl]
    __shared__ float                sh_UfT[Ff * 65];   // [f][j], padded rows
    __shared__ ull                  sh_mpk[Tt];        // packed nibble idx m(t,f)
    __shared__ __align__(16) ulonglong2 sh_tbld[16];   // {(cos,cos),(sin,sin)} dup pairs

    const int tid  = threadIdx.x;
    const int lane = tid & 31;
    const int w    = tid >> 5;            // 0 = (i,ste) warp, 1 = (c,o) warp
    const int bbase = blockIdx.x * 4;

    // ---- one-time staging ----
    {   // U: 2048 uint4 = 32 KB
        const uint4* gsrc = &g_Ub4[0][0];
        uint4* sdst = &sh_Ub[0][0][0];
        for (int i = tid; i < 2 * 32 * 32; i += 64) sdst[i] = gsrc[i];
    }
    const float* xg = x + (size_t)bbase * (Tt * Dd);
    for (int i = tid; i < Tt * Dd; i += 64) {
        sh_x4[i / Dd][i % Dd] = make_float4(xg[0 * Tt * Dd + i], xg[1 * Tt * Dd + i],
                                            xg[2 * Tt * Dd + i], xg[3 * Tt * Dd + i]);
    }
    for (int i = tid; i < Ff * Hh; i += 64) {
        int f = i / Hh, j = i % Hh;
        sh_UfT[f * 65 + j] = U_fre[j * Ff + f];
    }
    for (int i = tid; i < Tt; i += 64) {
        ull v = 0;
#pragma unroll
        for (int f = 1; f < Ff; f++)
            v |= (ull)(((i + 1) * f) % Ff) << (4 * f);
        sh_mpk[i] = v;
    }
    if (tid < Ff) {
        float s, c;
        sincosf((float)tid * 0.62831853071795864769f, &s, &c);   // 2*pi/10
        sh_tbld[tid] = make_ulonglong2(pack2(c, c), pack2(s, s));
    }
#pragma unroll
    for (int b = 0; b < 4; b++) sh_hd[tid][b] = 0ull;

    // ---- per-lane constants ----
    const int h0 = lane, h1 = lane + 32;
    const float* Wg0 = w ? W_c : W_i;
    const float* Wg1 = w ? W_o : W_ste;
    const float* bg0 = w ? b_c : b_i;
    const float* bg1 = w ? b_o : b_ste;
    ull Wp_[2][Dd];   // W as natural (g0,g1) pairs: [hslot][d]
#pragma unroll
    for (int d = 0; d < Dd; d++) {
        Wp_[0][d] = pack2(Wg0[d * Hh + h0], Wg1[d * Hh + h0]);
        Wp_[1][d] = pack2(Wg0[d * Hh + h1], Wg1[d * Hh + h1]);
    }
    const ull bp_[2] = { pack2(bg0[h0], bg1[h0]), pack2(bg0[h1], bg1[h1]) };
    const ull ba_p = pack2(b_a[h0], b_a[h1]);
    ull ua_d[Ff];
#pragma unroll
    for (int f = 0; f < Ff; f++) { float u = U_a[f]; ua_d[f] = pack2(u, u); }

    // fre duty: lanes 0..19 -> local batch fb = lane/10, freq ff = lane%10.
    const bool duty = (lane < 2 * Ff);
    const int  fb = lane / Ff, ff = lane % Ff;
    float wfre[Dd];
#pragma unroll
    for (int d = 0; d < Dd; d++) wfre[d] = W_fre[d * Ff + ff];
    const float bfre = b_fre[ff];

    // Oscillator state, hslot-PACKED: sre_p[bl][f] = (sre@h0, sre@h1)
    ull sre_p[2][Ff], sim_p[2][Ff];
#pragma unroll
    for (int bl = 0; bl < 2; bl++)
#pragma unroll
        for (int f = 0; f < Ff; f++) { sre_p[bl][f] = 0ull; sim_p[bl][f] = 0ull; }

    float hlast[2][2];   // [bl][hslot]

    __syncthreads();

    for (int t = 0; t < Tt; t++) {
        // ---- seeds: acc[hs][b] = (g0,g1) bias + x_t @ (Wg0,Wg1) ----
        ull acc[2][4];
#pragma unroll
        for (int b = 0; b < 4; b++) { acc[0][b] = bp_[0]; acc[1][b] = bp_[1]; }
        float af = bfre;
#pragma unroll
        for (int d = 0; d < Dd; d++) {
            float4 xv = sh_x4[t][d];             // LDS.128 broadcast
            ull x0 = pack2(xv.x, xv.x);
            ull x1 = pack2(xv.y, xv.y);
            ull x2 = pack2(xv.z, xv.z);
            ull x3 = pack2(xv.w, xv.w);
            acc[0][0] = fma2(x0, Wp_[0][d], acc[0][0]);
            acc[1][0] = fma2(x0, Wp_[1][d], acc[1][0]);
            acc[0][1] = fma2(x1, Wp_[0][d], acc[0][1]);
            acc[1][1] = fma2(x1, Wp_[1][d], acc[1][1]);
            acc[0][2] = fma2(x2, Wp_[0][d], acc[0][2]);
            acc[1][2] = fma2(x2, Wp_[1][d], acc[1][2]);
            acc[0][3] = fma2(x3, Wp_[0][d], acc[0][3]);
            acc[1][3] = fma2(x3, Wp_[1][d], acc[1][3]);
            float xd = fb ? (w ? xv.w : xv.y) : (w ? xv.z : xv.x);
            af = fmaf(xd, wfre[d], af);
        }

        // ---- recurrent matmul: paired bf16 U (1 LDS.128 per 2 j's) x dup-h ----
#pragma unroll 8
        for (int jp = 0; jp < 32; jp++) {
            uint4 uu = sh_Ub[w][jp][lane];       // LDS.128, conflict-free: j0 and j1
            int j0 = 2 * jp, j1 = 2 * jp + 1;
            {   // j0
                ulonglong2 hA = *(const ulonglong2*)&sh_hd[j0][0];
                ulonglong2 hB = *(const ulonglong2*)&sh_hd[j0][2];
                ull u0 = bf2f2(uu.x);
                ull u1 = bf2f2(uu.y);
                acc[0][0] = fma2(hA.x, u0, acc[0][0]);
                acc[1][0] = fma2(hA.x, u1, acc[1][0]);
                acc[0][1] = fma2(hA.y, u0, acc[0][1]);
                acc[1][1] = fma2(hA.y, u1, acc[1][1]);
                acc[0][2] = fma2(hB.x, u0, acc[0][2]);
                acc[1][2] = fma2(hB.x, u1, acc[1][2]);
                acc[0][3] = fma2(hB.y, u0, acc[0][3]);
                acc[1][3] = fma2(hB.y, u1, acc[1][3]);
                if (duty) {
                    ull hown = w ? (fb ? hB.y : hB.x) : (fb ? hA.y : hA.x);
                    af = fmaf(unpack2(hown).x, sh_UfT[ff * 65 + j0], af);
                }
            }
            {   // j1
                ulonglong2 hA = *(const ulonglong2*)&sh_hd[j1][0];
                ulonglong2 hB = *(const ulonglong2*)&sh_hd[j1][2];
                ull u0 = bf2f2(uu.z);
                ull u1 = bf2f2(uu.w);
                acc[0][0] = fma2(hA.x, u0, acc[0][0]);
                acc[1][0] = fma2(hA.x, u1, acc[1][0]);
                acc[0][1] = fma2(hA.y, u0, acc[0][1]);
                acc[1][1] = fma2(hA.y, u1, acc[1][1]);
                acc[0][2] = fma2(hB.x, u0, acc[0][2]);
                acc[1][2] = fma2(hB.x, u1, acc[1][2]);
                acc[0][3] = fma2(hB.y, u0, acc[0][3]);
                acc[1][3] = fma2(hB.y, u1, acc[1][3]);
                if (duty) {
                    ull hown = w ? (fb ? hB.y : hB.x) : (fb ? hA.y : hA.x);
                    af = fmaf(unpack2(hown).x, sh_UfT[ff * 65 + j1], af);
                }
            }
        }
        const float frev = hsig(af);   // valid on duty lanes

        // ---- exchange: send my gate pairs for the PEER's 2 batches ----
        {
            int pb = 2 * (1 - w);
            ulonglong2* dst = reinterpret_cast<ulonglong2*>(&sh_ex[w][lane][0]);
            dst[0] = make_ulonglong2(acc[0][pb],     acc[1][pb]);
            dst[1] = make_ulonglong2(acc[0][pb + 1], acc[1][pb + 1]);
        }
        __syncthreads();   // exchange visible; sh_hd reads of this step done
        ull peer[2][2];    // [bl][hs]
        {
            const ulonglong2* src = reinterpret_cast<const ulonglong2*>(&sh_ex[1 - w][lane][0]);
            ulonglong2 s0 = src[0], s1 = src[1];
            peer[0][0] = s0.x; peer[0][1] = s0.y;
            peer[1][0] = s1.x; peer[1][1] = s1.y;
        }

        // ---- elementwise tail, hslot-packed f32x2 ----
        const ull mp = sh_mpk[t];
#pragma unroll
        for (int bl = 0; bl < 2; bl++) {
            int b = 2 * w + bl;
            // gates (scalar, per hslot)
            float iv0, sv0, ov0, cv0, iv1, sv1, ov1, cv1;
            {
                float2 mine0 = unpack2(acc[0][b]);
                float2 thrs0 = unpack2(peer[bl][0]);
                float pi0   = w ? thrs0.x : mine0.x;
                float pste0 = w ? thrs0.y : mine0.y;
                float pc0   = w ? mine0.x : thrs0.x;
                float po0   = w ? mine0.y : thrs0.y;
                iv0 = hsig(pi0); sv0 = hsig(pste0); ov0 = hsig(po0);
                cv0 = iv0 * ftanh(pc0);
                float2 mine1 = unpack2(acc[1][b]);
                float2 thrs1 = unpack2(peer[bl][1]);
                float pi1   = w ? thrs1.x : mine1.x;
                float pste1 = w ? thrs1.y : mine1.y;
                float pc1   = w ? mine1.x : thrs1.x;
                float po1   = w ? mine1.y : thrs1.y;
                iv1 = hsig(pi1); sv1 = hsig(pste1); ov1 = hsig(po1);
                cv1 = iv1 * ftanh(pc1);
            }
            ull sv_p = pack2(sv0, sv1);
            ull cv_p = pack2(cv0, cv1);
            ull acca_p = ba_p;
#pragma unroll
            for (int f = 0; f < Ff; f++) {
                float frf = __shfl_sync(0xffffffffu, frev, bl * Ff + f);
                ull fr_p = pack2(frf, frf);
                ulonglong2 tb = sh_tbld[(int)((mp >> (4 * f)) & 15)];  // 1 LDS.128 bcast
                ull fv = mul2(sv_p, fr_p);
                ull r = fma2(fv, sre_p[bl][f], mul2(cv_p, tb.x));
                ull m = fma2(fv, sim_p[bl][f], mul2(cv_p, tb.y));
                sre_p[bl][f] = r;
                sim_p[bl][f] = m;
                ull A = fma2(m, m, mul2(r, r));
                acca_p = fma2(A, ua_d[f], acca_p);
            }
            float2 acca = unpack2(acca_p);
            hlast[bl][0] = ov0 * ftanh(acca.x);
            hlast[bl][1] = ov1 * ftanh(acca.y);
        }
        // Publish my 2 batches' h as dup pairs at both columns.
        {
            ulonglong2* r0 = reinterpret_cast<ulonglong2*>(&sh_hd[h0][2 * w]);
            ulonglong2* r1 = reinterpret_cast<ulonglong2*>(&sh_hd[h1][2 * w]);
            *r0 = make_ulonglong2(pack2(hlast[0][0], hlast[0][0]),
                                  pack2(hlast[1][0], hlast[1][0]));
            *r1 = make_ulonglong2(pack2(hlast[0][1], hlast[0][1]),
                                  pack2(hlast[1][1], hlast[1][1]));
        }
        __syncthreads();   // new h visible for next step
    }

    // ---- projection: out[b] = h @ W_p + b_p (warp butterfly over my 2 batches) ----
    {
        float wp0 = W_p[h0], wp1 = W_p[h1];
        float p0 = fmaf(hlast[0][0], wp0, hlast[0][1] * wp1);
        float p1 = fmaf(hlast[1][0], wp0, hlast[1][1] * wp1);
        ull pp = pack2(p0, p1);
#pragma unroll
        for (int off = 16; off >= 1; off >>= 1)
            pp = add2(pp, __shfl_xor_sync(0xffffffffu, pp, off));
        if (lane == 0) {
            float2 r = unpack2(pp);
            float bpv = b_p[0];
            out[bbase + 2 * w]     = r.x + bpv;
            out[bbase + 2 * w + 1] = r.y + bpv;
        }
    }
}

extern "C" void kernel_launch(void* const* d_in, const int* in_sizes, int n_in,
                              void* d_out, int out_size) {
    const float* x     = (const float*)d_in[0];
    const float* W_i   = (const float*)d_in[1];
    const float* U_i   = (const float*)d_in[2];
    const float* b_i   = (const float*)d_in[3];
    const float* W_ste = (const float*)d_in[4];
    const float* U_ste = (const float*)d_in[5];
    const float* b_ste = (const float*)d_in[6];
    const float* W_fre = (const float*)d_in[7];
    const float* U_fre = (const float*)d_in[8];
    const float* b_fre = (const float*)d_in[9];
    const float* W_c   = (const float*)d_in[10];
    const float* U_c   = (const float*)d_in[11];
    const float* b_c   = (const float*)d_in[12];
    const float* W_o   = (const float*)d_in[13];
    const float* U_o   = (const float*)d_in[14];
    const float* b_o   = (const float*)d_in[15];
    const float* U_a   = (const float*)d_in[16];
    const float* b_a   = (const float*)d_in[17];
    const float* W_p   = (const float*)d_in[18];
    const float* b_p   = (const float*)d_in[19];

    (void)in_sizes; (void)n_in; (void)out_size;

    prep_kernel<<<(2 * 32 * 32 + 255) / 256, 256>>>(U_i, U_ste, U_c, U_o);
    sfm_kernel<<<Bb / 4, 64>>>(x, W_i, b_i, W_ste, b_ste, W_fre, U_fre, b_fre,
                               W_c, b_c, W_o, b_o, U_a, b_a, W_p, b_p,
                               (float*)d_out);
}